// round 2
// baseline (speedup 1.0000x reference)
#include <cuda_runtime.h>

// Problem constants (fixed shapes)
#define DD 128   // obs dim
#define FF 80    // features
#define AA 18    // max actions
#define TM 128   // samples per block tile
#define NT 128   // threads per block
#define XST 132  // smem row stride for D-wide tiles (128+4), 16B-aligned rows
#define HST 84   // smem row stride for F-wide tiles (80+4), 16B-aligned rows

#define SMEM_FLOATS (TM * XST + FF * XST + 128 + 128)
#define SMEM_BYTES (SMEM_FLOATS * 4)

// Load a [rows x KDIM] row-major weight matrix into smem with row stride XST.
template <int KDIM>
__device__ __forceinline__ void load_w(float* sw, const float* __restrict__ gw,
                                       int rows, int tid) {
    const int K4 = KDIM / 4;
    const float4* g4 = (const float4*)gw;
    for (int i = tid; i < rows * K4; i += NT) {
        int f = i / K4;
        int k4 = i - f * K4;
        *(float4*)&sw[f * XST + k4 * 4] = g4[i];
    }
}

// Register-tiled GEMM: each thread computes acc[8][10] =
//   sb[f] + sum_k sa[m][k] * sw[f][k],  m = tx + i*16, f = ty*10 + j
template <int KDIM, int ASTRIDE>
__device__ __forceinline__ void gemm_tile(const float* __restrict__ sa,
                                          const float* __restrict__ sw,
                                          const float* __restrict__ sb,
                                          float acc[8][10], int tx, int ty) {
#pragma unroll
    for (int i = 0; i < 8; i++)
#pragma unroll
        for (int j = 0; j < 10; j++) acc[i][j] = sb[ty * 10 + j];

#pragma unroll 2
    for (int k = 0; k < KDIM; k += 4) {
        float4 a[8];
#pragma unroll
        for (int i = 0; i < 8; i++)
            a[i] = *(const float4*)&sa[(tx + i * 16) * ASTRIDE + k];
#pragma unroll
        for (int j = 0; j < 10; j++) {
            float4 w = *(const float4*)&sw[(ty * 10 + j) * XST + k];
#pragma unroll
            for (int i = 0; i < 8; i++) {
                acc[i][j] = fmaf(a[i].x, w.x, acc[i][j]);
                acc[i][j] = fmaf(a[i].y, w.y, acc[i][j]);
                acc[i][j] = fmaf(a[i].z, w.z, acc[i][j]);
                acc[i][j] = fmaf(a[i].w, w.w, acc[i][j]);
            }
        }
    }
}

__global__ void __launch_bounds__(NT, 2)
gym_fused(const float* __restrict__ state, const int* __restrict__ idx,
          const float* __restrict__ W1, const float* __restrict__ b1,
          const float* __restrict__ W2, const float* __restrict__ b2,
          const float* __restrict__ W3, const float* __restrict__ b3,
          const float* __restrict__ W4, const float* __restrict__ b4,
          float* __restrict__ out) {
    extern __shared__ float smem[];
    float* s_x = smem;                  // [TM][XST], aliased as s_h [TM][HST] later
    float* s_w = smem + TM * XST;       // [FF][XST] (W1/W2/W3/W4 + output staging)
    float* s_b = s_w + FF * XST;        // 128 floats (bias)
    int* s_idx = (int*)(s_b + 128);     // [TM]
    float* s_h = smem;                  // alias of s_x

    const int tid = threadIdx.x;
    const int tx = tid & 15;   // m-dim lane: m = tx + i*16
    const int ty = tid >> 4;   // f-dim lane: f = ty*10 + j
    const int m0 = blockIdx.x * TM;

    // ---- Load state tile [TM][DD] -> s_x (coalesced float4), and idx ----
    {
        const float4* gs = (const float4*)(state + (size_t)m0 * DD);
#pragma unroll
        for (int r = 0; r < TM * DD / 4; r += NT) {
            int i = r + tid;
            *(float4*)&s_x[(i >> 5) * XST + (i & 31) * 4] = gs[i];
        }
    }
    if (tid < TM) s_idx[tid] = idx[m0 + tid];
    __syncthreads();

    const int g_lo = s_idx[0];
    const int g_hi = s_idx[TM - 1];   // idx sorted -> tile games form [g_lo, g_hi]
    const int myg = s_idx[tid];

    float acc[8][10];

    // ---- Layer 1 (routed): h1 = relu(state @ W1[g].T + b1[g]) ----
    if (g_lo == g_hi) {
        // Fast path: single game in tile (all but ~7 of 2048 blocks)
        load_w<DD>(s_w, W1 + (size_t)g_lo * FF * DD, FF, tid);
        if (tid < FF) s_b[tid] = b1[g_lo * FF + tid];
        __syncthreads();
        gemm_tile<DD, XST>(s_x, s_w, s_b, acc, tx, ty);
    } else {
        // Boundary path: loop games present in tile, masked merge
        float hf[8][10];
#pragma unroll
        for (int i = 0; i < 8; i++)
#pragma unroll
            for (int j = 0; j < 10; j++) hf[i][j] = 0.0f;
        for (int g = g_lo; g <= g_hi; ++g) {
            __syncthreads();  // protect s_w/s_b from prior readers
            load_w<DD>(s_w, W1 + (size_t)g * FF * DD, FF, tid);
            if (tid < FF) s_b[tid] = b1[g * FF + tid];
            __syncthreads();
            gemm_tile<DD, XST>(s_x, s_w, s_b, acc, tx, ty);
#pragma unroll
            for (int i = 0; i < 8; i++) {
                if (s_idx[tx + i * 16] == g) {
#pragma unroll
                    for (int j = 0; j < 10; j++) hf[i][j] = acc[i][j];
                }
            }
        }
#pragma unroll
        for (int i = 0; i < 8; i++)
#pragma unroll
            for (int j = 0; j < 10; j++) acc[i][j] = hf[i][j];
    }

    __syncthreads();  // all s_x reads done; safe to alias as s_h
#pragma unroll
    for (int i = 0; i < 8; i++)
#pragma unroll
        for (int j = 0; j < 10; j++)
            s_h[(tx + i * 16) * HST + ty * 10 + j] = fmaxf(acc[i][j], 0.0f);

    // ---- Layer 2: h = relu(h1 @ W2.T + b2) ----
    load_w<FF>(s_w, W2, FF, tid);
    if (tid < FF) s_b[tid] = b2[tid];
    __syncthreads();
    gemm_tile<FF, HST>(s_h, s_w, s_b, acc, tx, ty);
    __syncthreads();  // all s_h / s_w reads done
#pragma unroll
    for (int i = 0; i < 8; i++)
#pragma unroll
        for (int j = 0; j < 10; j++)
            s_h[(tx + i * 16) * HST + ty * 10 + j] = fmaxf(acc[i][j], 0.0f);

    // ---- Layer 3: h = relu(h @ W3.T + b3) ----
    load_w<FF>(s_w, W3, FF, tid);
    if (tid < FF) s_b[tid] = b3[tid];
    __syncthreads();
    gemm_tile<FF, HST>(s_h, s_w, s_b, acc, tx, ty);
    __syncthreads();
#pragma unroll
    for (int i = 0; i < 8; i++)
#pragma unroll
        for (int j = 0; j < 10; j++)
            s_h[(tx + i * 16) * HST + ty * 10 + j] = fmaxf(acc[i][j], 0.0f);

    // ---- Layer 4 (routed head): q = h @ W4[g].T + b4[g]; thread <-> sample ----
    float q[AA];
#pragma unroll
    for (int a = 0; a < AA; a++) q[a] = 0.0f;

    for (int g = g_lo; g <= g_hi; ++g) {
        __syncthreads();  // protect s_w/s_b (first iter: also orders s_h writes)
        load_w<FF>(s_w, W4 + (size_t)g * AA * FF, AA, tid);
        if (tid < AA) s_b[tid] = b4[g * AA + tid];
        __syncthreads();
        if (myg == g) {
            float t[AA];
#pragma unroll
            for (int a = 0; a < AA; a++) t[a] = s_b[a];
#pragma unroll 2
            for (int k = 0; k < FF; k += 4) {
                float4 h = *(const float4*)&s_h[tid * HST + k];
#pragma unroll
                for (int a = 0; a < AA; a++) {
                    float4 w = *(const float4*)&s_w[a * XST + k];
                    t[a] = fmaf(h.x, w.x, t[a]);
                    t[a] = fmaf(h.y, w.y, t[a]);
                    t[a] = fmaf(h.z, w.z, t[a]);
                    t[a] = fmaf(h.w, w.w, t[a]);
                }
            }
#pragma unroll
            for (int a = 0; a < AA; a++) q[a] = t[a];
        }
    }

    // ---- Stage output through smem for fully-coalesced float4 stores ----
    __syncthreads();  // s_w reads done; reuse as staging
    float* s_out = s_w;
#pragma unroll
    for (int a = 0; a < AA; a++) s_out[tid * AA + a] = q[a];
    __syncthreads();
    {
        float4* go = (float4*)(out + (size_t)m0 * AA);
        const float4* so = (const float4*)s_out;
        for (int i = tid; i < TM * AA / 4; i += NT) go[i] = so[i];
    }
}

extern "C" void kernel_launch(void* const* d_in, const int* in_sizes, int n_in,
                              void* d_out, int out_size) {
    const float* state = (const float*)d_in[0];
    const int* idx     = (const int*)d_in[1];
    const float* W1    = (const float*)d_in[2];
    const float* b1    = (const float*)d_in[3];
    const float* W2    = (const float*)d_in[4];
    const float* b2    = (const float*)d_in[5];
    const float* W3    = (const float*)d_in[6];
    const float* b3    = (const float*)d_in[7];
    const float* W4    = (const float*)d_in[8];
    const float* b4    = (const float*)d_in[9];
    float* out = (float*)d_out;

    int B = in_sizes[0] / DD;
    int grid = B / TM;  // B = 262144 -> 2048 blocks

    cudaFuncSetAttribute(gym_fused, cudaFuncAttributeMaxDynamicSharedMemorySize,
                         SMEM_BYTES);
    gym_fused<<<grid, NT, SMEM_BYTES>>>(state, idx, W1, b1, W2, b2, W3, b3, W4,
                                        b4, out);
}

// round 7
// speedup vs baseline: 3.0382x; 3.0382x over previous
#include <cuda_runtime.h>
#include <cstdint>

#define DD 128   // obs dim
#define FF 80    // features
#define AA 18    // actions
#define TM 128   // samples per tile
#define NT 128   // threads (4 warps)
#define XS 132   // smem row stride (floats): 132*4 % 128 -> conflict-free frags

#define OFF_X 1024                        // X/H tile: [128][XS] floats
#define OFF_W (1024 + TM * XS * 4)        // W tile:   [80][XS] floats
#define SMEM_BYTES (OFF_W + FF * XS * 4)  // 110,848 B -> 2 CTAs/SM

// fp32 -> tf32 (round to nearest, keeps ~1e-4 accuracy)
__device__ __forceinline__ uint32_t f2tf(float f) {
    uint32_t u;
    asm("cvt.rna.tf32.f32 %0, %1;" : "=r"(u) : "f"(f));
    return u;
}

__device__ __forceinline__ void mma8(float c[4], const uint32_t a[4],
                                     const uint32_t b[2]) {
    asm volatile(
        "mma.sync.aligned.m16n8k8.row.col.f32.tf32.tf32.f32 "
        "{%0,%1,%2,%3}, {%4,%5,%6,%7}, {%8,%9}, {%0,%1,%2,%3};"
        : "+f"(c[0]), "+f"(c[1]), "+f"(c[2]), "+f"(c[3])
        : "r"(a[0]), "r"(a[1]), "r"(a[2]), "r"(a[3]), "r"(b[0]), "r"(b[1]));
}

// Warp-level GEMM: acc[mi][n][4] += Xtile[R0+mi*16 .. +16) x W[n*8 .. )^T
// A frag: row = l/4 (+8), col = l%4 (+4). B frag: n = l/4, k = l%4 (+4).
template <int KSTEPS, int NTILES>
__device__ __forceinline__ void mma_layer(const uint32_t* __restrict__ sx,
                                          const uint32_t* __restrict__ sw,
                                          float acc[2][NTILES][4], int R0,
                                          int l) {
    const int ar = (R0 + (l >> 2)) * XS + (l & 3);
    const int wr = (l >> 2) * XS + (l & 3);
#pragma unroll
    for (int k = 0; k < KSTEPS; ++k) {
        uint32_t A0[4], A1[4];
        const int b0 = ar + k * 8;
        A0[0] = sx[b0];           A0[1] = sx[b0 + 8 * XS];
        A0[2] = sx[b0 + 4];       A0[3] = sx[b0 + 8 * XS + 4];
        const int b1 = b0 + 16 * XS;
        A1[0] = sx[b1];           A1[1] = sx[b1 + 8 * XS];
        A1[2] = sx[b1 + 4];       A1[3] = sx[b1 + 8 * XS + 4];
#pragma unroll
        for (int n = 0; n < NTILES; ++n) {
            uint32_t B[2];
            const int wb = wr + n * 8 * XS + k * 8;
            B[0] = sw[wb];
            B[1] = sw[wb + 4];
            mma8(acc[0][n], A0, B);
            mma8(acc[1][n], A1, B);
        }
    }
}

__global__ void __launch_bounds__(NT, 2)
gym_mma(const float* __restrict__ state, const int* __restrict__ idx,
        const float* __restrict__ W1, const float* __restrict__ b1,
        const float* __restrict__ W2, const float* __restrict__ b2,
        const float* __restrict__ W3, const float* __restrict__ b3,
        const float* __restrict__ W4, const float* __restrict__ b4,
        float* __restrict__ out) {
    extern __shared__ char smem[];
    int* s_idx = (int*)smem;                 // 512 B
    float* s_bias = (float*)(smem + 512);    // 512 B
    uint32_t* sx = (uint32_t*)(smem + OFF_X);
    uint32_t* sw = (uint32_t*)(smem + OFF_W);

    const int tid = threadIdx.x;
    const int l = tid & 31;
    const int R0 = (tid >> 5) * 32;  // warp's 32 rows
    const int m0 = blockIdx.x * TM;

    // ---- Load idx + X tile (tf32-converted) ----
    s_idx[tid] = idx[m0 + tid];
    {
        const float4* gx = (const float4*)(state + (size_t)m0 * DD);
#pragma unroll
        for (int b = 0; b < TM * DD / 4; b += NT) {
            int i = b + tid;
            float4 v = gx[i];
            uint4 u = make_uint4(f2tf(v.x), f2tf(v.y), f2tf(v.z), f2tf(v.w));
            *(uint4*)&sx[(i >> 5) * XS + (i & 31) * 4] = u;
        }
    }
    __syncthreads();

    const int g_lo = s_idx[0];
    const int g_hi = s_idx[TM - 1];  // sorted idx -> tile games in [g_lo, g_hi]

    // row-game lookup for this thread's fragment rows (per m-tile: rows r, r+8)
    const int rg00 = s_idx[R0 + (l >> 2)];
    const int rg01 = s_idx[R0 + (l >> 2) + 8];
    const int rg10 = s_idx[R0 + 16 + (l >> 2)];
    const int rg11 = s_idx[R0 + 16 + (l >> 2) + 8];

    // ================= Layer 1 (routed, K=128, N=80) =================
    float facc[2][10][4];
    for (int g = g_lo; g <= g_hi; ++g) {
        __syncthreads();  // prior iter's mma done with s_w
        {
            const float4* gw = (const float4*)(W1 + (size_t)g * FF * DD);
#pragma unroll
            for (int b = 0; b < FF * DD / 4; b += NT) {
                int i = b + tid;
                float4 v = gw[i];
                uint4 u = make_uint4(f2tf(v.x), f2tf(v.y), f2tf(v.z), f2tf(v.w));
                *(uint4*)&sw[(i >> 5) * XS + (i & 31) * 4] = u;
            }
            if (tid < FF) s_bias[tid] = b1[g * FF + tid];
        }
        __syncthreads();

        float acc[2][10][4];
#pragma unroll
        for (int mi = 0; mi < 2; ++mi)
#pragma unroll
            for (int n = 0; n < 10; ++n) {
                float bv0 = s_bias[n * 8 + 2 * (l & 3)];
                float bv1 = s_bias[n * 8 + 2 * (l & 3) + 1];
                acc[mi][n][0] = bv0; acc[mi][n][1] = bv1;
                acc[mi][n][2] = bv0; acc[mi][n][3] = bv1;
            }
        mma_layer<16, 10>(sx, sw, acc, R0, l);

        const bool t00 = (rg00 == g), t01 = (rg01 == g);
        const bool t10 = (rg10 == g), t11 = (rg11 == g);
#pragma unroll
        for (int n = 0; n < 10; ++n) {
            if (t00) { facc[0][n][0] = acc[0][n][0]; facc[0][n][1] = acc[0][n][1]; }
            if (t01) { facc[0][n][2] = acc[0][n][2]; facc[0][n][3] = acc[0][n][3]; }
            if (t10) { facc[1][n][0] = acc[1][n][0]; facc[1][n][1] = acc[1][n][1]; }
            if (t11) { facc[1][n][2] = acc[1][n][2]; facc[1][n][3] = acc[1][n][3]; }
        }
    }
    __syncthreads();  // all mma reads of sx done
#pragma unroll
    for (int mi = 0; mi < 2; ++mi) {
        int r = R0 + mi * 16 + (l >> 2);
#pragma unroll
        for (int n = 0; n < 10; ++n) {
            int c = n * 8 + 2 * (l & 3);
            sx[r * XS + c]           = f2tf(fmaxf(facc[mi][n][0], 0.f));
            sx[r * XS + c + 1]       = f2tf(fmaxf(facc[mi][n][1], 0.f));
            sx[(r + 8) * XS + c]     = f2tf(fmaxf(facc[mi][n][2], 0.f));
            sx[(r + 8) * XS + c + 1] = f2tf(fmaxf(facc[mi][n][3], 0.f));
        }
    }
    __syncthreads();

    // ================= Layers 2 & 3 (shared, K=80, N=80) =================
#pragma unroll 1
    for (int layer = 0; layer < 2; ++layer) {
        const float* Wl = layer ? W3 : W2;
        const float* bl = layer ? b3 : b2;
        {
            const float4* gw = (const float4*)Wl;
#pragma unroll
            for (int b = 0; b < FF * FF / 4; b += NT) {
                int i = b + tid;
                if (i < FF * FF / 4) {
                    float4 v = gw[i];
                    uint4 u = make_uint4(f2tf(v.x), f2tf(v.y), f2tf(v.z), f2tf(v.w));
                    *(uint4*)&sw[(i / 20) * XS + (i % 20) * 4] = u;
                }
            }
            if (tid < FF) s_bias[tid] = bl[tid];
        }
        __syncthreads();

        float acc[2][10][4];
#pragma unroll
        for (int mi = 0; mi < 2; ++mi)
#pragma unroll
            for (int n = 0; n < 10; ++n) {
                float bv0 = s_bias[n * 8 + 2 * (l & 3)];
                float bv1 = s_bias[n * 8 + 2 * (l & 3) + 1];
                acc[mi][n][0] = bv0; acc[mi][n][1] = bv1;
                acc[mi][n][2] = bv0; acc[mi][n][3] = bv1;
            }
        mma_layer<10, 10>(sx, sw, acc, R0, l);
        __syncthreads();  // mma reads of sx done before overwrite
#pragma unroll
        for (int mi = 0; mi < 2; ++mi) {
            int r = R0 + mi * 16 + (l >> 2);
#pragma unroll
            for (int n = 0; n < 10; ++n) {
                int c = n * 8 + 2 * (l & 3);
                sx[r * XS + c]           = f2tf(fmaxf(acc[mi][n][0], 0.f));
                sx[r * XS + c + 1]       = f2tf(fmaxf(acc[mi][n][1], 0.f));
                sx[(r + 8) * XS + c]     = f2tf(fmaxf(acc[mi][n][2], 0.f));
                sx[(r + 8) * XS + c + 1] = f2tf(fmaxf(acc[mi][n][3], 0.f));
            }
        }
        __syncthreads();
    }

    // ================= Layer 4 (routed head, N=18 padded to 24) =================
    // zero pad rows 18..23 of W (cols 0..79), once
    for (int i = tid; i < 6 * 20; i += NT) {
        *(uint4*)&sw[(18 + i / 20) * XS + (i % 20) * 4] =
            make_uint4(0u, 0u, 0u, 0u);
    }

    float facc4[2][3][4];
    for (int g = g_lo; g <= g_hi; ++g) {
        __syncthreads();  // zero-pad visible / prior mma done with s_w
        {
            const float4* gw = (const float4*)(W4 + (size_t)g * AA * FF);
            for (int i = tid; i < AA * FF / 4; i += NT) {
                float4 v = gw[i];
                uint4 u = make_uint4(f2tf(v.x), f2tf(v.y), f2tf(v.z), f2tf(v.w));
                *(uint4*)&sw[(i / 20) * XS + (i % 20) * 4] = u;
            }
            if (tid < 32) s_bias[tid] = (tid < AA) ? b4[g * AA + tid] : 0.f;
        }
        __syncthreads();

        float acc[2][3][4];
#pragma unroll
        for (int mi = 0; mi < 2; ++mi)
#pragma unroll
            for (int n = 0; n < 3; ++n) {
                float bv0 = s_bias[n * 8 + 2 * (l & 3)];
                float bv1 = s_bias[n * 8 + 2 * (l & 3) + 1];
                acc[mi][n][0] = bv0; acc[mi][n][1] = bv1;
                acc[mi][n][2] = bv0; acc[mi][n][3] = bv1;
            }
        mma_layer<10, 3>(sx, sw, acc, R0, l);

        const bool t00 = (rg00 == g), t01 = (rg01 == g);
        const bool t10 = (rg10 == g), t11 = (rg11 == g);
#pragma unroll
        for (int n = 0; n < 3; ++n) {
            if (t00) { facc4[0][n][0] = acc[0][n][0]; facc4[0][n][1] = acc[0][n][1]; }
            if (t01) { facc4[0][n][2] = acc[0][n][2]; facc4[0][n][3] = acc[0][n][3]; }
            if (t10) { facc4[1][n][0] = acc[1][n][0]; facc4[1][n][1] = acc[1][n][1]; }
            if (t11) { facc4[1][n][2] = acc[1][n][2]; facc4[1][n][3] = acc[1][n][3]; }
        }
    }

    // stage q through smem (s_w region, free now) for coalesced stores
    __syncthreads();
    float* s_out = (float*)sw;  // [128][18]
#pragma unroll
    for (int mi = 0; mi < 2; ++mi) {
        int r = R0 + mi * 16 + (l >> 2);
#pragma unroll
        for (int n = 0; n < 3; ++n) {
            int c = n * 8 + 2 * (l & 3);
            if (c < AA) {
                s_out[r * AA + c]       = facc4[mi][n][0];
                s_out[(r + 8) * AA + c] = facc4[mi][n][2];
                if (c + 1 < AA) {
                    s_out[r * AA + c + 1]       = facc4[mi][n][1];
                    s_out[(r + 8) * AA + c + 1] = facc4[mi][n][3];
                }
            }
        }
    }
    __syncthreads();
    {
        float* go = out + (size_t)m0 * AA;
        for (int i = tid; i < TM * AA; i += NT) go[i] = s_out[i];
    }
}

extern "C" void kernel_launch(void* const* d_in, const int* in_sizes, int n_in,
                              void* d_out, int out_size) {
    const float* state = (const float*)d_in[0];
    const int* idx     = (const int*)d_in[1];
    const float* W1    = (const float*)d_in[2];
    const float* b1    = (const float*)d_in[3];
    const float* W2    = (const float*)d_in[4];
    const float* b2    = (const float*)d_in[5];
    const float* W3    = (const float*)d_in[6];
    const float* b3    = (const float*)d_in[7];
    const float* W4    = (const float*)d_in[8];
    const float* b4    = (const float*)d_in[9];
    float* out = (float*)d_out;

    int B = in_sizes[0] / DD;
    int grid = B / TM;

    cudaFuncSetAttribute(gym_mma, cudaFuncAttributeMaxDynamicSharedMemorySize,
                         SMEM_BYTES);
    gym_mma<<<grid, NT, SMEM_BYTES>>>(state, idx, W1, b1, W2, b2, W3, b3, W4,
                                      b4, out);
}